// round 6
// baseline (speedup 1.0000x reference)
#include <cuda_runtime.h>
#include <cuda_fp16.h>
#include <cstdint>

#define NE 8
#define NT 256
#define ND 2048
#define NH 8192

// 32 MB fp16 scratch for mid = silu(x@w1) * (x@w3), [E, T, H]
__device__ __align__(256) __half g_mid[(size_t)NE * NT * NH];

// ---------------- helpers ----------------
__device__ __forceinline__ uint32_t smem_u32(const void* p) {
    uint32_t a;
    asm("{ .reg .u64 t; cvta.to.shared.u64 t, %1; cvt.u32.u64 %0, t; }" : "=r"(a) : "l"(p));
    return a;
}
__device__ __forceinline__ uint32_t swz(uint32_t o) { return o ^ ((o >> 3) & 0x70); }

__device__ __forceinline__ uint32_t pack2(float x, float y) {
    __half2 h = __floats2half2_rn(x, y);
    return *reinterpret_cast<uint32_t*>(&h);
}

__device__ __forceinline__ void ldsm4(uint32_t* r, uint32_t a) {
    asm volatile("ldmatrix.sync.aligned.m8n8.x4.shared.b16 {%0,%1,%2,%3}, [%4];"
        : "=r"(r[0]), "=r"(r[1]), "=r"(r[2]), "=r"(r[3]) : "r"(a));
}
__device__ __forceinline__ void ldsm4t(uint32_t* r, uint32_t a) {
    asm volatile("ldmatrix.sync.aligned.m8n8.x4.trans.shared.b16 {%0,%1,%2,%3}, [%4];"
        : "=r"(r[0]), "=r"(r[1]), "=r"(r[2]), "=r"(r[3]) : "r"(a));
}
__device__ __forceinline__ void mma_f16(float* c, const uint32_t* a, const uint32_t* b) {
    asm volatile("mma.sync.aligned.m16n8k16.row.col.f32.f16.f16.f32 "
        "{%0,%1,%2,%3}, {%4,%5,%6,%7}, {%8,%9}, {%0,%1,%2,%3};"
        : "+f"(c[0]), "+f"(c[1]), "+f"(c[2]), "+f"(c[3])
        : "r"(a[0]), "r"(a[1]), "r"(a[2]), "r"(a[3]), "r"(b[0]), "r"(b[1]));
}

__device__ __forceinline__ float silu_mul(float a, float g) {
    return a * g / (1.0f + __expf(-a));
}

// =====================================================================
// Kernel 1: mid = silu(x @ w1) * (x @ w3)
// CTA tile: M=128 (tokens) x N=64 (H), two fp32 accumulators (h1, h3).
// K chunk = 64 over D. 256 threads, 8 warps as 4(M) x 2(N); warp tile 32x32.
// Smem/stage (32 KB): A[m=128][k=64] fp16 | B1[k=64][n=64] fp16 | B3 same.
// A fragments: ldmatrix.x4; B (k-major rows, n contiguous): ldmatrix.x4.trans.
// =====================================================================
#define KC  64
#define ST1 32768
#define B1_OFF 16384
#define B3_OFF 24576

__global__ void __launch_bounds__(256, 1)
moe_k1(const float* __restrict__ x, const float* __restrict__ w1,
       const float* __restrict__ w3)
{
    extern __shared__ char smem[];
    const uint32_t sb = smem_u32(smem);
    const int tid = threadIdx.x;
    const int e  = blockIdx.z;
    const int t0 = blockIdx.x * 128;   // t-tile fastest for L2 weight reuse
    const int h0 = blockIdx.y * 64;

    const float* pX  = x  + ((size_t)e * NT + t0) * ND;
    const float* pW1 = w1 + (size_t)e * ND * NH + h0;
    const float* pW3 = w3 + (size_t)e * ND * NH + h0;

    // --- load mapping: 16 threads per 64-float row ---
    const int rr = tid >> 4;    // 0..15 row base
    const int sg = tid & 15;    // float4 segment
    uint32_t sts[8];
    #pragma unroll
    for (int i = 0; i < 8; ++i)
        sts[i] = swz((uint32_t)((rr + 16 * i) * 128 + sg * 8));

    uint32_t rgA[8][2], rgB1[4][2], rgB3[4][2];

    auto LOAD = [&](int c) {
        const int d0 = c * KC;
        #pragma unroll
        for (int i = 0; i < 8; ++i) {
            float4 v = *(const float4*)(pX + (size_t)(rr + 16 * i) * ND + d0 + sg * 4);
            rgA[i][0] = pack2(v.x, v.y); rgA[i][1] = pack2(v.z, v.w);
        }
        #pragma unroll
        for (int i = 0; i < 4; ++i) {
            const size_t go = (size_t)(d0 + rr + 16 * i) * NH + sg * 4;
            float4 v = *(const float4*)(pW1 + go);
            rgB1[i][0] = pack2(v.x, v.y); rgB1[i][1] = pack2(v.z, v.w);
            float4 u = *(const float4*)(pW3 + go);
            rgB3[i][0] = pack2(u.x, u.y); rgB3[i][1] = pack2(u.z, u.w);
        }
    };
    auto STORE = [&](int s) {
        char* base = smem + s * ST1;
        #pragma unroll
        for (int i = 0; i < 8; ++i)
            *(uint2*)(base + sts[i]) = make_uint2(rgA[i][0], rgA[i][1]);
        #pragma unroll
        for (int i = 0; i < 4; ++i) {
            *(uint2*)(base + B1_OFF + sts[i]) = make_uint2(rgB1[i][0], rgB1[i][1]);
            *(uint2*)(base + B3_OFF + sts[i]) = make_uint2(rgB3[i][0], rgB3[i][1]);
        }
    };

    // --- compute mapping ---
    const int wid = tid >> 5, lane = tid & 31;
    const int wm = (wid & 3) * 32;
    const int wn = (wid >> 2) * 32;
    const int lr = lane & 7, lg = lane >> 3;
    const uint32_t a_row = (uint32_t)(wm + lr + (lg & 1) * 8);   // A smem row
    const uint32_t a_kx  = (uint32_t)((lg >> 1) * 16);           // A k-byte extra
    const uint32_t b_kr  = (uint32_t)(lr + (lg & 1) * 8);        // B k-row within 16
    const uint32_t b_nx  = (uint32_t)(wn * 2 + (lg >> 1) * 16);  // B n-byte

    float acc1[2][4][4] = {};
    float acc3[2][4][4] = {};

    auto COMPUTE = [&](int s) {
        const uint32_t base = sb + (uint32_t)s * ST1;
        #pragma unroll
        for (int ks = 0; ks < 4; ++ks) {
            uint32_t a[2][4];
            #pragma unroll
            for (int mt = 0; mt < 2; ++mt)
                ldsm4(a[mt], base + swz((a_row + mt * 16) * 128 + ks * 32 + a_kx));
            uint32_t b1[2][4], b3[2][4];
            #pragma unroll
            for (int nt = 0; nt < 2; ++nt) {
                const uint32_t off = swz((ks * 16 + b_kr) * 128 + b_nx + nt * 32);
                ldsm4t(b1[nt], base + B1_OFF + off);
                ldsm4t(b3[nt], base + B3_OFF + off);
            }
            #pragma unroll
            for (int mt = 0; mt < 2; ++mt)
                #pragma unroll
                for (int j = 0; j < 4; ++j) {
                    mma_f16(acc1[mt][j], a[mt], &b1[j >> 1][(j & 1) * 2]);
                    mma_f16(acc3[mt][j], a[mt], &b3[j >> 1][(j & 1) * 2]);
                }
        }
    };

    LOAD(0); STORE(0); __syncthreads();
    const int NC = ND / KC;   // 32
    for (int c = 0; c < NC; ++c) {
        if (c + 1 < NC) LOAD(c + 1);
        COMPUTE(c & 1);
        if (c + 1 < NC) STORE((c + 1) & 1);
        __syncthreads();
    }

    // --- epilogue: silu(h1) * h3 -> fp16 g_mid ---
    const int l4 = lane >> 2, l2 = (lane & 3) * 2;
    #pragma unroll
    for (int mt = 0; mt < 2; ++mt)
        #pragma unroll
        for (int i = 0; i < 2; ++i) {
            const int row = t0 + wm + mt * 16 + l4 + i * 8;
            __half* mp = g_mid + ((size_t)e * NT + row) * NH + h0 + wn + l2;
            #pragma unroll
            for (int j = 0; j < 4; ++j) {
                float ox = silu_mul(acc1[mt][j][i * 2],     acc3[mt][j][i * 2]);
                float oy = silu_mul(acc1[mt][j][i * 2 + 1], acc3[mt][j][i * 2 + 1]);
                *(uint32_t*)(mp + j * 8) = pack2(ox, oy);
            }
        }
}

// =====================================================================
// Kernel 2: out = mid @ w2^T.  out[t,d] = sum_h mid[t,h] * w2[d,h]
// CTA tile: M=128 x N=128. K chunk = 64 over H. 8 warps 4(M) x 2(N),
// warp tile 32x64. Smem/stage (32 KB): A[m=128][k=64] | B[n=128][k=64].
// A from fp16 g_mid (raw uint4). B rows are k-contiguous -> ldmatrix.x4.
// =====================================================================
#define ST2 32768
#define B2_OFF 16384

__global__ void __launch_bounds__(256, 1)
moe_k2(const float* __restrict__ w2, float* __restrict__ out)
{
    extern __shared__ char smem[];
    const uint32_t sb = smem_u32(smem);
    const int tid = threadIdx.x;
    const int e  = blockIdx.z;
    const int t0 = blockIdx.x * 128;
    const int n0 = blockIdx.y * 128;

    const __half* pA = g_mid + ((size_t)e * NT + t0) * NH;
    const float*  pB = w2 + ((size_t)e * ND + n0) * NH;

    // A: 8 threads per 128B row, 4 passes of 32 rows
    const int ra = tid >> 3, s8 = tid & 7;
    // B: 16 threads per 64-float row, 8 passes of 16 rows
    const int rb = tid >> 4, sg = tid & 15;

    uint32_t stsA[4], stsB[8];
    #pragma unroll
    for (int i = 0; i < 4; ++i) stsA[i] = swz((uint32_t)((ra + 32 * i) * 128 + s8 * 16));
    #pragma unroll
    for (int i = 0; i < 8; ++i) stsB[i] = swz((uint32_t)((rb + 16 * i) * 128 + sg * 8));

    uint4 rgA[4]; uint32_t rgB[8][2];

    auto LOAD = [&](int c) {
        const int k0 = c * KC;
        #pragma unroll
        for (int i = 0; i < 4; ++i)
            rgA[i] = *(const uint4*)(pA + (size_t)(ra + 32 * i) * NH + k0 + s8 * 8);
        #pragma unroll
        for (int i = 0; i < 8; ++i) {
            float4 v = *(const float4*)(pB + (size_t)(rb + 16 * i) * NH + k0 + sg * 4);
            rgB[i][0] = pack2(v.x, v.y); rgB[i][1] = pack2(v.z, v.w);
        }
    };
    auto STORE = [&](int s) {
        char* base = smem + s * ST2;
        #pragma unroll
        for (int i = 0; i < 4; ++i)
            *(uint4*)(base + stsA[i]) = rgA[i];
        #pragma unroll
        for (int i = 0; i < 8; ++i)
            *(uint2*)(base + B2_OFF + stsB[i]) = make_uint2(rgB[i][0], rgB[i][1]);
    };

    const int wid = tid >> 5, lane = tid & 31;
    const int wm = (wid & 3) * 32;
    const int wn = (wid >> 2) * 64;
    const int lr = lane & 7, lg = lane >> 3;
    const uint32_t a_row  = (uint32_t)(wm + lr + (lg & 1) * 8);
    const uint32_t a_kx   = (uint32_t)((lg >> 1) * 16);
    const uint32_t b_nrow = (uint32_t)(wn + lr + (lg >> 1) * 8);  // B n-row
    const uint32_t b_kx   = (uint32_t)((lg & 1) * 16);            // B k-byte

    float acc[2][8][4] = {};

    auto COMPUTE = [&](int s) {
        const uint32_t base = sb + (uint32_t)s * ST2;
        #pragma unroll
        for (int ks = 0; ks < 4; ++ks) {
            uint32_t a[2][4];
            #pragma unroll
            for (int mt = 0; mt < 2; ++mt)
                ldsm4(a[mt], base + swz((a_row + mt * 16) * 128 + ks * 32 + a_kx));
            uint32_t b[4][4];
            #pragma unroll
            for (int nt = 0; nt < 4; ++nt)
                ldsm4(b[nt], base + B2_OFF +
                      swz((b_nrow + nt * 16) * 128 + ks * 32 + b_kx));
            #pragma unroll
            for (int mt = 0; mt < 2; ++mt)
                #pragma unroll
                for (int j = 0; j < 8; ++j)
                    mma_f16(acc[mt][j], a[mt], &b[j >> 1][(j & 1) * 2]);
        }
    };

    LOAD(0); STORE(0); __syncthreads();
    const int NC = NH / KC;   // 128
    for (int c = 0; c < NC; ++c) {
        if (c + 1 < NC) LOAD(c + 1);
        COMPUTE(c & 1);
        if (c + 1 < NC) STORE((c + 1) & 1);
        __syncthreads();
    }

    // --- epilogue: fp32 out ---
    const int l4 = lane >> 2, l2 = (lane & 3) * 2;
    #pragma unroll
    for (int mt = 0; mt < 2; ++mt)
        #pragma unroll
        for (int i = 0; i < 2; ++i) {
            const int row = t0 + wm + mt * 16 + l4 + i * 8;
            float* op = out + ((size_t)e * NT + row) * ND + n0 + wn + l2;
            #pragma unroll
            for (int j = 0; j < 8; ++j) {
                float2 v = make_float2(acc[mt][j][i * 2], acc[mt][j][i * 2 + 1]);
                *(float2*)(op + j * 8) = v;
            }
        }
}

// =====================================================================
extern "C" void kernel_launch(void* const* d_in, const int* in_sizes, int n_in,
                              void* d_out, int out_size)
{
    (void)in_sizes; (void)n_in; (void)out_size;
    const float* x  = (const float*)d_in[0];
    const float* w1 = (const float*)d_in[1];
    const float* w2 = (const float*)d_in[2];
    const float* w3 = (const float*)d_in[3];
    float* out = (float*)d_out;

    static bool attr_done = false;
    // (set every call; cheap and deterministic — no guard needed)
    cudaFuncSetAttribute(moe_k1, cudaFuncAttributeMaxDynamicSharedMemorySize, 2 * ST1);
    cudaFuncSetAttribute(moe_k2, cudaFuncAttributeMaxDynamicSharedMemorySize, 2 * ST2);
    (void)attr_done;

    dim3 g1(NT / 128, NH / 64, NE);    // (2, 128, 8) — t fastest
    moe_k1<<<g1, 256, 2 * ST1>>>(x, w1, w3);

    dim3 g2(NT / 128, ND / 128, NE);   // (2, 16, 8)
    moe_k2<<<g2, 256, 2 * ST2>>>(w2, out);
}

// round 7
// speedup vs baseline: 1.3212x; 1.3212x over previous
#include <cuda_runtime.h>
#include <cuda_fp16.h>
#include <cstdint>

#define NE 8
#define NT 256
#define ND 2048
#define NH 8192

// 32 MB fp16 scratch for mid = silu(x@w1) * (x@w3), [E, T, H]
__device__ __align__(256) __half g_mid[(size_t)NE * NT * NH];

// ---------------- helpers ----------------
__device__ __forceinline__ uint32_t smem_u32(const void* p) {
    uint32_t a;
    asm("{ .reg .u64 t; cvta.to.shared.u64 t, %1; cvt.u32.u64 %0, t; }" : "=r"(a) : "l"(p));
    return a;
}
__device__ __forceinline__ uint32_t swz(uint32_t o) { return o ^ ((o >> 3) & 0x70); }

__device__ __forceinline__ uint32_t pack2(float x, float y) {
    __half2 h = __floats2half2_rn(x, y);
    return *reinterpret_cast<uint32_t*>(&h);
}

__device__ __forceinline__ void ldsm4(uint32_t* r, uint32_t a) {
    asm volatile("ldmatrix.sync.aligned.m8n8.x4.shared.b16 {%0,%1,%2,%3}, [%4];"
        : "=r"(r[0]), "=r"(r[1]), "=r"(r[2]), "=r"(r[3]) : "r"(a));
}
__device__ __forceinline__ void ldsm4t(uint32_t* r, uint32_t a) {
    asm volatile("ldmatrix.sync.aligned.m8n8.x4.trans.shared.b16 {%0,%1,%2,%3}, [%4];"
        : "=r"(r[0]), "=r"(r[1]), "=r"(r[2]), "=r"(r[3]) : "r"(a));
}
__device__ __forceinline__ void mma_f16(float* c, const uint32_t* a, const uint32_t* b) {
    asm volatile("mma.sync.aligned.m16n8k16.row.col.f32.f16.f16.f32 "
        "{%0,%1,%2,%3}, {%4,%5,%6,%7}, {%8,%9}, {%0,%1,%2,%3};"
        : "+f"(c[0]), "+f"(c[1]), "+f"(c[2]), "+f"(c[3])
        : "r"(a[0]), "r"(a[1]), "r"(a[2]), "r"(a[3]), "r"(b[0]), "r"(b[1]));
}
__device__ __forceinline__ void cp16(uint32_t dst, const void* src) {
    asm volatile("cp.async.cg.shared.global [%0], [%1], 16;" :: "r"(dst), "l"(src) : "memory");
}
#define CP_COMMIT() asm volatile("cp.async.commit_group;" ::: "memory")
#define CP_WAIT1()  asm volatile("cp.async.wait_group 1;" ::: "memory")
#define CP_WAIT0()  asm volatile("cp.async.wait_group 0;" ::: "memory")

__device__ __forceinline__ float silu_mul(float a, float g) {
    return a * g / (1.0f + __expf(-a));
}

#define KC 64

// =====================================================================
// Kernel 1: mid = silu(x @ w1) * (x @ w3)
// CTA: M=128 x N=64, K-chunk 64, 3-stage smem, 256 thr (4M x 2N warps),
// warp tile 32x32 with dual accumulators. 2 CTAs/SM.
// Stage (32 KB): A[128][64] fp16 | B1[k64][n64] | B3[k64][n64].
// A (x, L2-resident): direct LDG->cvt->STS. B1/B3 (DRAM): reg-staged,
// STS after COMPUTE to hide DRAM latency in-warp.
// =====================================================================
#define K1_STG 32768
#define K1_B1  16384
#define K1_B3  24576

__global__ void __launch_bounds__(256, 2)
moe_k1(const float* __restrict__ x, const float* __restrict__ w1,
       const float* __restrict__ w3)
{
    extern __shared__ char smem[];
    const uint32_t sb = smem_u32(smem);
    const int tid = threadIdx.x;
    const int e  = blockIdx.z;
    const int t0 = blockIdx.x * 128;   // t fastest: L2 weight reuse across t-tiles
    const int h0 = blockIdx.y * 64;

    const float* pX  = x  + ((size_t)e * NT + t0) * ND;
    const float* pW1 = w1 + (size_t)e * ND * NH + h0;
    const float* pW3 = w3 + (size_t)e * ND * NH + h0;

    const int rr = tid >> 4;   // 0..15
    const int sg = tid & 15;   // float4 segment

    uint32_t rgB1[4][2], rgB3[4][2];

    auto A_STS = [&](int c, int s) {
        char* base = smem + s * K1_STG;
        const int d0 = c * KC;
        #pragma unroll
        for (int i = 0; i < 8; ++i) {
            const int row = rr + 16 * i;
            float4 v = *(const float4*)(pX + (size_t)row * ND + d0 + sg * 4);
            *(uint2*)(base + swz((uint32_t)(row * 128 + sg * 8))) =
                make_uint2(pack2(v.x, v.y), pack2(v.z, v.w));
        }
    };
    auto B_LDG = [&](int c) {
        const int d0 = c * KC;
        #pragma unroll
        for (int i = 0; i < 4; ++i) {
            const size_t go = (size_t)(d0 + rr + 16 * i) * NH + sg * 4;
            float4 v = *(const float4*)(pW1 + go);
            rgB1[i][0] = pack2(v.x, v.y); rgB1[i][1] = pack2(v.z, v.w);
            float4 u = *(const float4*)(pW3 + go);
            rgB3[i][0] = pack2(u.x, u.y); rgB3[i][1] = pack2(u.z, u.w);
        }
    };
    auto B_STS = [&](int s) {
        char* base = smem + s * K1_STG;
        #pragma unroll
        for (int i = 0; i < 4; ++i) {
            const uint32_t o = swz((uint32_t)((rr + 16 * i) * 128 + sg * 8));
            *(uint2*)(base + K1_B1 + o) = make_uint2(rgB1[i][0], rgB1[i][1]);
            *(uint2*)(base + K1_B3 + o) = make_uint2(rgB3[i][0], rgB3[i][1]);
        }
    };

    // --- compute mapping (identical to R6-validated) ---
    const int wid = tid >> 5, lane = tid & 31;
    const int wm = (wid & 3) * 32;
    const int wn = (wid >> 2) * 32;
    const int lr = lane & 7, lg = lane >> 3;
    const uint32_t a_row = (uint32_t)(wm + lr + (lg & 1) * 8);
    const uint32_t a_kx  = (uint32_t)((lg >> 1) * 16);
    const uint32_t b_kr  = (uint32_t)(lr + (lg & 1) * 8);
    const uint32_t b_nx  = (uint32_t)(wn * 2 + (lg >> 1) * 16);

    float acc1[2][4][4] = {};
    float acc3[2][4][4] = {};

    auto COMPUTE = [&](int s) {
        const uint32_t base = sb + (uint32_t)s * K1_STG;
        #pragma unroll
        for (int ks = 0; ks < 4; ++ks) {
            uint32_t a[2][4];
            #pragma unroll
            for (int mt = 0; mt < 2; ++mt)
                ldsm4(a[mt], base + swz((a_row + mt * 16) * 128 + ks * 32 + a_kx));
            uint32_t b1[2][4], b3[2][4];
            #pragma unroll
            for (int nt = 0; nt < 2; ++nt) {
                const uint32_t off = swz((ks * 16 + b_kr) * 128 + b_nx + nt * 32);
                ldsm4t(b1[nt], base + K1_B1 + off);
                ldsm4t(b3[nt], base + K1_B3 + off);
            }
            #pragma unroll
            for (int mt = 0; mt < 2; ++mt)
                #pragma unroll
                for (int j = 0; j < 4; ++j) {
                    mma_f16(acc1[mt][j], a[mt], &b1[j >> 1][(j & 1) * 2]);
                    mma_f16(acc3[mt][j], a[mt], &b3[j >> 1][(j & 1) * 2]);
                }
        }
    };

    // prologue: fill stages 0,1
    B_LDG(0); A_STS(0, 0); B_STS(0);
    B_LDG(1); A_STS(1, 1); B_STS(1);
    __syncthreads();

    const int NC = ND / KC;   // 32
    for (int c = 0; c < NC; ++c) {
        if (c + 2 < NC) { B_LDG(c + 2); A_STS(c + 2, (c + 2) % 3); }
        COMPUTE(c % 3);
        if (c + 2 < NC) B_STS((c + 2) % 3);
        __syncthreads();
    }

    // --- epilogue: silu(h1) * h3 -> fp16 g_mid ---
    const int l4 = lane >> 2, l2 = (lane & 3) * 2;
    #pragma unroll
    for (int mt = 0; mt < 2; ++mt)
        #pragma unroll
        for (int i = 0; i < 2; ++i) {
            const int row = t0 + wm + mt * 16 + l4 + i * 8;
            __half* mp = g_mid + ((size_t)e * NT + row) * NH + h0 + wn + l2;
            #pragma unroll
            for (int j = 0; j < 4; ++j) {
                float ox = silu_mul(acc1[mt][j][i * 2],     acc3[mt][j][i * 2]);
                float oy = silu_mul(acc1[mt][j][i * 2 + 1], acc3[mt][j][i * 2 + 1]);
                *(uint32_t*)(mp + j * 8) = pack2(ox, oy);
            }
        }
}

// =====================================================================
// Kernel 2: out = mid @ w2^T
// CTA: M=128 x N=64, K-chunk 64, 3-stage smem, 256 thr (4M x 2N warps),
// warp tile 32x32. 2 CTAs/SM.
// Stage (24 KB): A[128][64] fp16 | B[n64][k64] fp16.
// A (g_mid fp16): cp.async, no regs, no stall. B (w2, DRAM): reg-staged.
// =====================================================================
#define K2_STG 24576
#define K2_B   16384

__global__ void __launch_bounds__(256, 2)
moe_k2(const float* __restrict__ w2, float* __restrict__ out)
{
    extern __shared__ char smem[];
    const uint32_t sb = smem_u32(smem);
    const int tid = threadIdx.x;
    const int e  = blockIdx.z;
    const int t0 = blockIdx.x * 128;
    const int n0 = blockIdx.y * 64;

    const __half* pA = g_mid + ((size_t)e * NT + t0) * NH;
    const float*  pB = w2 + ((size_t)e * ND + n0) * NH;

    const int ra = tid >> 3, s8 = tid & 7;    // A: 32 rows x 8 segs, 4 iters
    const int rr = tid >> 4, sg = tid & 15;   // B: 16 rows x 16 segs, 4 iters

    uint32_t rgB[4][2];

    auto A_CP = [&](int c, int s) {
        const uint32_t base = sb + (uint32_t)s * K2_STG;
        const int k0 = c * KC;
        #pragma unroll
        for (int i = 0; i < 4; ++i) {
            const int row = ra + 32 * i;
            cp16(base + swz((uint32_t)(row * 128 + s8 * 16)),
                 pA + (size_t)row * NH + k0 + s8 * 8);
        }
        CP_COMMIT();
    };
    auto B_LDG = [&](int c) {
        const int k0 = c * KC;
        #pragma unroll
        for (int i = 0; i < 4; ++i) {
            float4 v = *(const float4*)(pB + (size_t)(rr + 16 * i) * NH + k0 + sg * 4);
            rgB[i][0] = pack2(v.x, v.y); rgB[i][1] = pack2(v.z, v.w);
        }
    };
    auto B_STS = [&](int s) {
        char* base = smem + s * K2_STG + K2_B;
        #pragma unroll
        for (int i = 0; i < 4; ++i)
            *(uint2*)(base + swz((uint32_t)((rr + 16 * i) * 128 + sg * 8))) =
                make_uint2(rgB[i][0], rgB[i][1]);
    };

    const int wid = tid >> 5, lane = tid & 31;
    const int wm = (wid & 3) * 32;
    const int wn = (wid >> 2) * 32;
    const int lr = lane & 7, lg = lane >> 3;
    const uint32_t a_row  = (uint32_t)(wm + lr + (lg & 1) * 8);
    const uint32_t a_kx   = (uint32_t)((lg >> 1) * 16);
    const uint32_t b_nrow = (uint32_t)(wn + lr + (lg >> 1) * 8);
    const uint32_t b_kx   = (uint32_t)((lg & 1) * 16);

    float acc[2][4][4] = {};

    auto COMPUTE = [&](int s) {
        const uint32_t base = sb + (uint32_t)s * K2_STG;
        #pragma unroll
        for (int ks = 0; ks < 4; ++ks) {
            uint32_t a[2][4];
            #pragma unroll
            for (int mt = 0; mt < 2; ++mt)
                ldsm4(a[mt], base + swz((a_row + mt * 16) * 128 + ks * 32 + a_kx));
            uint32_t b[2][4];
            #pragma unroll
            for (int nt = 0; nt < 2; ++nt)
                ldsm4(b[nt], base + K2_B +
                      swz((b_nrow + nt * 16) * 128 + ks * 32 + b_kx));
            #pragma unroll
            for (int mt = 0; mt < 2; ++mt)
                #pragma unroll
                for (int j = 0; j < 4; ++j)
                    mma_f16(acc[mt][j], a[mt], &b[j >> 1][(j & 1) * 2]);
        }
    };

    // prologue
    A_CP(0, 0); B_LDG(0); B_STS(0);
    A_CP(1, 1); B_LDG(1); B_STS(1);
    CP_WAIT0();
    __syncthreads();

    const int NC = NH / KC;   // 128
    for (int c = 0; c < NC; ++c) {
        if (c + 2 < NC) { A_CP(c + 2, (c + 2) % 3); B_LDG(c + 2); }
        COMPUTE(c % 3);
        if (c + 2 < NC) { B_STS((c + 2) % 3); CP_WAIT1(); }
        else            { CP_WAIT0(); }
        __syncthreads();
    }

    // --- epilogue: fp32 out ---
    const int l4 = lane >> 2, l2 = (lane & 3) * 2;
    #pragma unroll
    for (int mt = 0; mt < 2; ++mt)
        #pragma unroll
        for (int i = 0; i < 2; ++i) {
            const int row = t0 + wm + mt * 16 + l4 + i * 8;
            float* op = out + ((size_t)e * NT + row) * ND + n0 + wn + l2;
            #pragma unroll
            for (int j = 0; j < 4; ++j)
                *(float2*)(op + j * 8) =
                    make_float2(acc[mt][j][i * 2], acc[mt][j][i * 2 + 1]);
        }
}

// =====================================================================
extern "C" void kernel_launch(void* const* d_in, const int* in_sizes, int n_in,
                              void* d_out, int out_size)
{
    (void)in_sizes; (void)n_in; (void)out_size;
    const float* x  = (const float*)d_in[0];
    const float* w1 = (const float*)d_in[1];
    const float* w2 = (const float*)d_in[2];
    const float* w3 = (const float*)d_in[3];
    float* out = (float*)d_out;

    cudaFuncSetAttribute(moe_k1, cudaFuncAttributeMaxDynamicSharedMemorySize, 3 * K1_STG);
    cudaFuncSetAttribute(moe_k2, cudaFuncAttributeMaxDynamicSharedMemorySize, 3 * K2_STG);

    dim3 g1(NT / 128, NH / 64, NE);    // (2, 128, 8)
    moe_k1<<<g1, 256, 3 * K1_STG>>>(x, w1, w3);

    dim3 g2(NT / 128, ND / 64, NE);    // (2, 32, 8)
    moe_k2<<<g2, 256, 3 * K2_STG>>>(w2, out);
}

// round 8
// speedup vs baseline: 1.3832x; 1.0469x over previous
#include <cuda_runtime.h>
#include <cuda_fp16.h>
#include <cstdint>

#define NE 8
#define NT 256
#define ND 2048
#define NH 8192

// 32 MB fp16 scratch for mid = silu(x@w1) * (x@w3), [E, T, H]
__device__ __align__(256) __half g_mid[(size_t)NE * NT * NH];

// ---------------- helpers ----------------
__device__ __forceinline__ uint32_t smem_u32(const void* p) {
    uint32_t a;
    asm("{ .reg .u64 t; cvta.to.shared.u64 t, %1; cvt.u32.u64 %0, t; }" : "=r"(a) : "l"(p));
    return a;
}
__device__ __forceinline__ uint32_t swz(uint32_t o) { return o ^ ((o >> 3) & 0x70); }

__device__ __forceinline__ uint32_t pack2(float x, float y) {
    __half2 h = __floats2half2_rn(x, y);
    return *reinterpret_cast<uint32_t*>(&h);
}

__device__ __forceinline__ void ldsm4(uint32_t* r, uint32_t a) {
    asm volatile("ldmatrix.sync.aligned.m8n8.x4.shared.b16 {%0,%1,%2,%3}, [%4];"
        : "=r"(r[0]), "=r"(r[1]), "=r"(r[2]), "=r"(r[3]) : "r"(a));
}
__device__ __forceinline__ void ldsm4t(uint32_t* r, uint32_t a) {
    asm volatile("ldmatrix.sync.aligned.m8n8.x4.trans.shared.b16 {%0,%1,%2,%3}, [%4];"
        : "=r"(r[0]), "=r"(r[1]), "=r"(r[2]), "=r"(r[3]) : "r"(a));
}
__device__ __forceinline__ void mma_f16(float* c, const uint32_t* a, const uint32_t* b) {
    asm volatile("mma.sync.aligned.m16n8k16.row.col.f32.f16.f16.f32 "
        "{%0,%1,%2,%3}, {%4,%5,%6,%7}, {%8,%9}, {%0,%1,%2,%3};"
        : "+f"(c[0]), "+f"(c[1]), "+f"(c[2]), "+f"(c[3])
        : "r"(a[0]), "r"(a[1]), "r"(a[2]), "r"(a[3]), "r"(b[0]), "r"(b[1]));
}
__device__ __forceinline__ void cp16(uint32_t dst, const void* src) {
    asm volatile("cp.async.cg.shared.global [%0], [%1], 16;" :: "r"(dst), "l"(src) : "memory");
}
#define CP_COMMIT() asm volatile("cp.async.commit_group;" ::: "memory")
#define CP_WAIT0()  asm volatile("cp.async.wait_group 0;" ::: "memory")

__device__ __forceinline__ float silu_mul(float a, float g) {
    return a * g / (1.0f + __expf(-a));
}

#define KC 64

// =====================================================================
// Kernel 1 (unchanged from R7): mid = silu(x @ w1) * (x @ w3)
// CTA M=128 x N=64, 3-stage, 256 thr, warp tile 32x32 dual-acc, 2 CTA/SM.
// =====================================================================
#define K1_STG 32768
#define K1_B1  16384
#define K1_B3  24576

__global__ void __launch_bounds__(256, 2)
moe_k1(const float* __restrict__ x, const float* __restrict__ w1,
       const float* __restrict__ w3)
{
    extern __shared__ char smem[];
    const uint32_t sb = smem_u32(smem);
    const int tid = threadIdx.x;
    const int e  = blockIdx.z;
    const int t0 = blockIdx.x * 128;
    const int h0 = blockIdx.y * 64;

    const float* pX  = x  + ((size_t)e * NT + t0) * ND;
    const float* pW1 = w1 + (size_t)e * ND * NH + h0;
    const float* pW3 = w3 + (size_t)e * ND * NH + h0;

    const int rr = tid >> 4;
    const int sg = tid & 15;

    uint32_t rgB1[4][2], rgB3[4][2];

    auto A_STS = [&](int c, int s) {
        char* base = smem + s * K1_STG;
        const int d0 = c * KC;
        #pragma unroll
        for (int i = 0; i < 8; ++i) {
            const int row = rr + 16 * i;
            float4 v = *(const float4*)(pX + (size_t)row * ND + d0 + sg * 4);
            *(uint2*)(base + swz((uint32_t)(row * 128 + sg * 8))) =
                make_uint2(pack2(v.x, v.y), pack2(v.z, v.w));
        }
    };
    auto B_LDG = [&](int c) {
        const int d0 = c * KC;
        #pragma unroll
        for (int i = 0; i < 4; ++i) {
            const size_t go = (size_t)(d0 + rr + 16 * i) * NH + sg * 4;
            float4 v = *(const float4*)(pW1 + go);
            rgB1[i][0] = pack2(v.x, v.y); rgB1[i][1] = pack2(v.z, v.w);
            float4 u = *(const float4*)(pW3 + go);
            rgB3[i][0] = pack2(u.x, u.y); rgB3[i][1] = pack2(u.z, u.w);
        }
    };
    auto B_STS = [&](int s) {
        char* base = smem + s * K1_STG;
        #pragma unroll
        for (int i = 0; i < 4; ++i) {
            const uint32_t o = swz((uint32_t)((rr + 16 * i) * 128 + sg * 8));
            *(uint2*)(base + K1_B1 + o) = make_uint2(rgB1[i][0], rgB1[i][1]);
            *(uint2*)(base + K1_B3 + o) = make_uint2(rgB3[i][0], rgB3[i][1]);
        }
    };

    const int wid = tid >> 5, lane = tid & 31;
    const int wm = (wid & 3) * 32;
    const int wn = (wid >> 2) * 32;
    const int lr = lane & 7, lg = lane >> 3;
    const uint32_t a_row = (uint32_t)(wm + lr + (lg & 1) * 8);
    const uint32_t a_kx  = (uint32_t)((lg >> 1) * 16);
    const uint32_t b_kr  = (uint32_t)(lr + (lg & 1) * 8);
    const uint32_t b_nx  = (uint32_t)(wn * 2 + (lg >> 1) * 16);

    float acc1[2][4][4] = {};
    float acc3[2][4][4] = {};

    auto COMPUTE = [&](int s) {
        const uint32_t base = sb + (uint32_t)s * K1_STG;
        #pragma unroll
        for (int ks = 0; ks < 4; ++ks) {
            uint32_t a[2][4];
            #pragma unroll
            for (int mt = 0; mt < 2; ++mt)
                ldsm4(a[mt], base + swz((a_row + mt * 16) * 128 + ks * 32 + a_kx));
            uint32_t b1[2][4], b3[2][4];
            #pragma unroll
            for (int nt = 0; nt < 2; ++nt) {
                const uint32_t off = swz((ks * 16 + b_kr) * 128 + b_nx + nt * 32);
                ldsm4t(b1[nt], base + K1_B1 + off);
                ldsm4t(b3[nt], base + K1_B3 + off);
            }
            #pragma unroll
            for (int mt = 0; mt < 2; ++mt)
                #pragma unroll
                for (int j = 0; j < 4; ++j) {
                    mma_f16(acc1[mt][j], a[mt], &b1[j >> 1][(j & 1) * 2]);
                    mma_f16(acc3[mt][j], a[mt], &b3[j >> 1][(j & 1) * 2]);
                }
        }
    };

    B_LDG(0); A_STS(0, 0); B_STS(0);
    B_LDG(1); A_STS(1, 1); B_STS(1);
    __syncthreads();

    const int NC = ND / KC;   // 32
    for (int c = 0; c < NC; ++c) {
        if (c + 2 < NC) { B_LDG(c + 2); A_STS(c + 2, (c + 2) % 3); }
        COMPUTE(c % 3);
        if (c + 2 < NC) B_STS((c + 2) % 3);
        __syncthreads();
    }

    const int l4 = lane >> 2, l2 = (lane & 3) * 2;
    #pragma unroll
    for (int mt = 0; mt < 2; ++mt)
        #pragma unroll
        for (int i = 0; i < 2; ++i) {
            const int row = t0 + wm + mt * 16 + l4 + i * 8;
            __half* mp = g_mid + ((size_t)e * NT + row) * NH + h0 + wn + l2;
            #pragma unroll
            for (int j = 0; j < 4; ++j) {
                float ox = silu_mul(acc1[mt][j][i * 2],     acc3[mt][j][i * 2]);
                float oy = silu_mul(acc1[mt][j][i * 2 + 1], acc3[mt][j][i * 2 + 1]);
                *(uint32_t*)(mp + j * 8) = pack2(ox, oy);
            }
        }
}

// =====================================================================
// Kernel 2: out = mid @ w2^T
// 512 thr, 1 CTA/SM (cap 128 regs). CTA M=128 x N=256, 16 warps 4Mx4N,
// warp tile 32x64 (R6-validated mapping). KC=64, 4 stages, sync per 2 chunks.
// Stage (48 KB): A[128][64] fp16 @0 (cp.async) | B[n256][k64] fp16 @16K.
// Grid (2,8,8) = 128 CTAs = single wave.
// =====================================================================
#define K2_STG 49152
#define K2_B   16384

__global__ void __launch_bounds__(512, 1)
moe_k2(const float* __restrict__ w2, float* __restrict__ out)
{
    extern __shared__ char smem[];
    const uint32_t sb = smem_u32(smem);
    const int tid = threadIdx.x;
    const int e  = blockIdx.z;
    const int t0 = blockIdx.x * 128;
    const int n0 = blockIdx.y * 256;

    const __half* pA = g_mid + ((size_t)e * NT + t0) * NH;
    const float*  pB = w2 + ((size_t)e * ND + n0) * NH;

    // A: 4 thr/row (2 x cp16 each), 128 rows
    const int ra = tid >> 2, s4 = tid & 3;
    // B: 16 thr/row, 32 rows/pass, 8 passes = 256 rows
    const int rb = tid >> 4, sg = tid & 15;

    uint32_t rgB[8][2];

    auto A_CP = [&](int c, int s) {
        const uint32_t base = sb + (uint32_t)s * K2_STG;
        const int k0 = c * KC;
        const __half* src = pA + (size_t)ra * NH + k0 + s4 * 16;
        cp16(base + swz((uint32_t)(ra * 128 + s4 * 32)),      src);
        cp16(base + swz((uint32_t)(ra * 128 + s4 * 32 + 16)), src + 8);
        CP_COMMIT();
    };
    auto B_LDG = [&](int c) {
        const int k0 = c * KC;
        #pragma unroll
        for (int i = 0; i < 8; ++i) {
            float4 v = *(const float4*)(pB + (size_t)(rb + 32 * i) * NH + k0 + sg * 4);
            rgB[i][0] = pack2(v.x, v.y); rgB[i][1] = pack2(v.z, v.w);
        }
    };
    auto B_STS = [&](int s) {
        char* base = smem + s * K2_STG + K2_B;
        #pragma unroll
        for (int i = 0; i < 8; ++i)
            *(uint2*)(base + swz((uint32_t)((rb + 32 * i) * 128 + sg * 8))) =
                make_uint2(rgB[i][0], rgB[i][1]);
    };

    const int wid = tid >> 5, lane = tid & 31;
    const int wm = (wid & 3) * 32;
    const int wn = (wid >> 2) * 64;
    const int lr = lane & 7, lg = lane >> 3;
    const uint32_t a_row  = (uint32_t)(wm + lr + (lg & 1) * 8);
    const uint32_t a_kx   = (uint32_t)((lg >> 1) * 16);
    const uint32_t b_nrow = (uint32_t)(wn + lr + (lg >> 1) * 8);
    const uint32_t b_kx   = (uint32_t)((lg & 1) * 16);

    float acc[2][8][4] = {};

    auto COMPUTE = [&](int s) {
        const uint32_t base = sb + (uint32_t)s * K2_STG;
        #pragma unroll
        for (int ks = 0; ks < 4; ++ks) {
            uint32_t a[2][4];
            #pragma unroll
            for (int mt = 0; mt < 2; ++mt)
                ldsm4(a[mt], base + swz((a_row + mt * 16) * 128 + ks * 32 + a_kx));
            uint32_t b[4][4];
            #pragma unroll
            for (int nt = 0; nt < 4; ++nt)
                ldsm4(b[nt], base + K2_B +
                      swz((b_nrow + nt * 16) * 128 + ks * 32 + b_kx));
            #pragma unroll
            for (int mt = 0; mt < 2; ++mt)
                #pragma unroll
                for (int j = 0; j < 8; ++j)
                    mma_f16(acc[mt][j], a[mt], &b[j >> 1][(j & 1) * 2]);
        }
    };

    // prologue: fill stages 0..3 (chunks 0..3)
    #pragma unroll
    for (int p = 0; p < 4; ++p) {
        B_LDG(p); B_STS(p); A_CP(p, p);
    }
    CP_WAIT0();
    __syncthreads();

    const int NC = NH / KC;   // 128
    for (int c = 0; c < NC; c += 2) {
        if (c + 4 < NC) B_LDG(c + 4);       // DRAM latency covered by 2 COMPUTEs
        COMPUTE(c & 3);
        COMPUTE((c + 1) & 3);
        CP_WAIT0();
        __syncthreads();
        if (c + 4 < NC) { A_CP(c + 4, c & 3); B_STS(c & 3); }
        if (c + 5 < NC) { B_LDG(c + 5); A_CP(c + 5, (c + 1) & 3); B_STS((c + 1) & 3); }
    }

    // --- epilogue: fp32 out ---
    const int l4 = lane >> 2, l2 = (lane & 3) * 2;
    #pragma unroll
    for (int mt = 0; mt < 2; ++mt)
        #pragma unroll
        for (int i = 0; i < 2; ++i) {
            const int row = t0 + wm + mt * 16 + l4 + i * 8;
            float* op = out + ((size_t)e * NT + row) * ND + n0 + wn + l2;
            #pragma unroll
            for (int j = 0; j < 8; ++j)
                *(float2*)(op + j * 8) =
                    make_float2(acc[mt][j][i * 2], acc[mt][j][i * 2 + 1]);
        }
}

// =====================================================================
extern "C" void kernel_launch(void* const* d_in, const int* in_sizes, int n_in,
                              void* d_out, int out_size)
{
    (void)in_sizes; (void)n_in; (void)out_size;
    const float* x  = (const float*)d_in[0];
    const float* w1 = (const float*)d_in[1];
    const float* w2 = (const float*)d_in[2];
    const float* w3 = (const float*)d_in[3];
    float* out = (float*)d_out;

    cudaFuncSetAttribute(moe_k1, cudaFuncAttributeMaxDynamicSharedMemorySize, 3 * K1_STG);
    cudaFuncSetAttribute(moe_k2, cudaFuncAttributeMaxDynamicSharedMemorySize, 4 * K2_STG);

    dim3 g1(NT / 128, NH / 64, NE);    // (2, 128, 8)
    moe_k1<<<g1, 256, 3 * K1_STG>>>(x, w1, w3);

    dim3 g2(NT / 128, ND / 256, NE);   // (2, 8, 8) — 128 CTAs, 1 wave
    moe_k2<<<g2, 512, 4 * K2_STG>>>(w2, out);
}